// round 11
// baseline (speedup 1.0000x reference)
#include <cuda_runtime.h>
#include <cuda_bf16.h>
#include <cstdint>

#define N_SITES 100000
#define DIM 128
#define HID 512
#define KVOL 343

typedef unsigned short u16;
typedef unsigned int u32;

// ---------------- scratch (hi/lo bf16 planes) ----------------
__device__ __align__(16) u16 g_xh[(size_t)N_SITES * DIM];
__device__ __align__(16) u16 g_xl[(size_t)N_SITES * DIM];
__device__ __align__(16) u16 g_hh[(size_t)N_SITES * HID];
__device__ __align__(16) u16 g_hl[(size_t)N_SITES * HID];
__device__ __align__(16) u16 g_w1h[DIM * HID];   // [k][n]
__device__ __align__(16) u16 g_w1l[DIM * HID];
__device__ __align__(16) u16 g_w2h[HID * DIM];   // [k][n], pre-scaled by GRN
__device__ __align__(16) u16 g_w2l[HID * DIM];
__device__ float g_ssq[HID];
__device__ float g_scale[HID];
__device__ float g_c2[DIM];

// ---------------- helpers ----------------
__device__ __forceinline__ void split_hl(float f, u16& h, u16& l) {
    __nv_bfloat16 hb = __float2bfloat16(f);
    h = __bfloat16_as_ushort(hb);
    l = __bfloat16_as_ushort(__float2bfloat16(f - __bfloat162float(hb)));
}
__device__ __forceinline__ float gelu_exact(float x) {
    return 0.5f * x * (1.0f + erff(x * 0.7071067811865475f));
}
__device__ __forceinline__ void ldsm4(uint32_t r[4], const void* p) {
    uint32_t a = (uint32_t)__cvta_generic_to_shared(p);
    asm volatile("ldmatrix.sync.aligned.m8n8.x4.shared.b16 {%0,%1,%2,%3}, [%4];"
                 : "=r"(r[0]), "=r"(r[1]), "=r"(r[2]), "=r"(r[3]) : "r"(a));
}
__device__ __forceinline__ void ldsm4t(uint32_t r[4], const void* p) {
    uint32_t a = (uint32_t)__cvta_generic_to_shared(p);
    asm volatile("ldmatrix.sync.aligned.m8n8.x4.trans.shared.b16 {%0,%1,%2,%3}, [%4];"
                 : "=r"(r[0]), "=r"(r[1]), "=r"(r[2]), "=r"(r[3]) : "r"(a));
}
__device__ __forceinline__ void mma16816(float c[4], const uint32_t a[4],
                                         uint32_t b0, uint32_t b1) {
    asm volatile(
        "mma.sync.aligned.m16n8k16.row.col.f32.bf16.bf16.f32 "
        "{%0,%1,%2,%3},{%4,%5,%6,%7},{%8,%9},{%0,%1,%2,%3};"
        : "+f"(c[0]), "+f"(c[1]), "+f"(c[2]), "+f"(c[3])
        : "r"(a[0]), "r"(a[1]), "r"(a[2]), "r"(a[3]), "r"(b0), "r"(b1));
}
__device__ __forceinline__ void cpa16(u16* dst, const u16* src, bool valid) {
    uint32_t d = (uint32_t)__cvta_generic_to_shared(dst);
    int sz = valid ? 16 : 0;
    asm volatile("cp.async.cg.shared.global [%0], [%1], 16, %2;\n"
                 :: "r"(d), "l"(src), "r"(sz));
}
__device__ __forceinline__ void cpa_commit() {
    asm volatile("cp.async.commit_group;\n");
}

// ---------------- init: zero ssq + c2 = b2 + grn_b @ w2 ----------------
__global__ void k_init(const float* __restrict__ grn_b, const float* __restrict__ w2,
                       const float* __restrict__ b2) {
    __shared__ float part[4][DIM];
    int t = threadIdx.x;  // 512
    g_ssq[t] = 0.0f;
    int jg = t >> 7, col = t & 127;
    float s = 0.f;
    #pragma unroll 4
    for (int j = jg * 128; j < jg * 128 + 128; j++)
        s = fmaf(grn_b[j], w2[(size_t)j * DIM + col], s);
    part[jg][col] = s;
    __syncthreads();
    if (t < DIM) g_c2[t] = b2[t] + part[0][t] + part[1][t] + part[2][t] + part[3][t];
}

// ---------------- prep: split w1 into hi/lo planes [k][n] ----------------
__global__ void k_w1prep(const float* __restrict__ w1) {
    int idx = blockIdx.x * 512 + threadIdx.x;  // 128 x 512
    float f = w1[idx];
    u16 h, l;
    split_hl(f, h, l);
    g_w1h[idx] = h;
    g_w1l[idx] = l;
}

// ---------------- prep: split (scale[k] * w2) into hi/lo planes [k][n] ----------------
__global__ void k_w2prep(const float* __restrict__ w2) {
    int idx = blockIdx.x * 512 + threadIdx.x;  // 512 x 512... grid 128, k = idx>>7
    int k = idx >> 7;
    float f = g_scale[k] * w2[idx];
    u16 h, l;
    split_hl(f, h, l);
    g_w2h[idx] = h;
    g_w2l[idx] = l;
}

// ---------------- kernel 1: sparse depthwise conv + LayerNorm -> hi/lo planes ----------------
__global__ __launch_bounds__(256) void k_dwln(
    const float* __restrict__ feats, const int* __restrict__ nidx,
    const float* __restrict__ dww, const float* __restrict__ dwb,
    const float* __restrict__ lng, const float* __restrict__ lnb) {
    int warp = (blockIdx.x * blockDim.x + threadIdx.x) >> 5;
    int lane = threadIdx.x & 31;
    if (warp >= N_SITES) return;

    const int* nb = nidx + (size_t)warp * KVOL;
    float4 acc = make_float4(0.f, 0.f, 0.f, 0.f);

    #pragma unroll 1
    for (int base = 0; base < KVOL; base += 32) {
        int k = base + lane;
        int idx = (k < KVOL) ? __ldg(nb + k) : N_SITES;
        unsigned m = __ballot_sync(0xffffffffu, idx < N_SITES);
        while (m) {
            int b = __ffs(m) - 1;
            m &= m - 1;
            int id = __shfl_sync(0xffffffffu, idx, b);
            int kk = base + b;
            float4 f = *(const float4*)(feats + (size_t)id * DIM + lane * 4);
            float4 w = *(const float4*)(dww + (size_t)kk * DIM + lane * 4);
            acc.x = fmaf(f.x, w.x, acc.x);
            acc.y = fmaf(f.y, w.y, acc.y);
            acc.z = fmaf(f.z, w.z, acc.z);
            acc.w = fmaf(f.w, w.w, acc.w);
        }
    }
    float4 bb = *(const float4*)(dwb + lane * 4);
    acc.x += bb.x; acc.y += bb.y; acc.z += bb.z; acc.w += bb.w;

    float s = acc.x + acc.y + acc.z + acc.w;
    float q = acc.x * acc.x + acc.y * acc.y + acc.z * acc.z + acc.w * acc.w;
    #pragma unroll
    for (int o = 16; o; o >>= 1) {
        s += __shfl_xor_sync(0xffffffffu, s, o);
        q += __shfl_xor_sync(0xffffffffu, q, o);
    }
    float mu = s * (1.0f / DIM);
    float var = q * (1.0f / DIM) - mu * mu;
    float rs = rsqrtf(var + 1e-6f);

    float4 g = *(const float4*)(lng + lane * 4);
    float4 be = *(const float4*)(lnb + lane * 4);
    float o0 = (acc.x - mu) * rs * g.x + be.x;
    float o1 = (acc.y - mu) * rs * g.y + be.y;
    float o2 = (acc.z - mu) * rs * g.z + be.z;
    float o3 = (acc.w - mu) * rs * g.w + be.w;
    u16 h0, l0, h1, l1, h2, l2, h3, l3;
    split_hl(o0, h0, l0); split_hl(o1, h1, l1);
    split_hl(o2, h2, l2); split_hl(o3, h3, l3);
    size_t off = (size_t)warp * DIM + lane * 4;
    *(uint2*)(g_xh + off) = make_uint2((u32)h0 | ((u32)h1 << 16), (u32)h2 | ((u32)h3 << 16));
    *(uint2*)(g_xl + off) = make_uint2((u32)l0 | ((u32)l1 << 16), (u32)l2 | ((u32)l3 << 16));
}

// ---------------- GEMM common: 128x128 tile, BK=32, 256 thr, 2-stage cp.async ----------------
// smem layout (u16 units per stage): A_hi@0 (128x40), A_lo@5120, B_hi@10240 (32x136), B_lo@14592
#define SM_ALO 5120
#define SM_BHI 10240
#define SM_BLO 14592
#define SM_STAGE 18944
#define SMEM_BYTES (2 * SM_STAGE * 2)

// pass-major MMA: 8 independent accumulator chains per pass (breaks RAW stalls)
__device__ __forceinline__ void mma_tile(const u16* base, int lane, int mw, int nw,
                                         float acc[2][8][4]) {
    #pragma unroll
    for (int ks = 0; ks < 2; ks++) {
        uint32_t ah[2][4], al[2][4];
        #pragma unroll
        for (int mf = 0; mf < 2; mf++) {
            int arow = mw * 32 + mf * 16 + (lane & 15);
            int acol = ks * 16 + 8 * (lane >> 4);
            ldsm4(ah[mf], base + arow * 40 + acol);
            ldsm4(al[mf], base + SM_ALO + arow * 40 + acol);
        }
        #pragma unroll
        for (int p = 0; p < 2; p++) {
            uint32_t bh[2][4], bl[2][4];
            #pragma unroll
            for (int g = 0; g < 2; g++) {
                int ng = p * 2 + g;
                int brow = ks * 16 + (lane & 15);
                int bcol = nw * 64 + ng * 16 + 8 * (lane >> 4);
                ldsm4t(bh[g], base + SM_BHI + brow * 136 + bcol);
                ldsm4t(bl[g], base + SM_BLO + brow * 136 + bcol);
            }
            // pass 1: Ah * Bh
            #pragma unroll
            for (int g = 0; g < 2; g++)
                #pragma unroll
                for (int mf = 0; mf < 2; mf++) {
                    mma16816(acc[mf][(p * 2 + g) * 2], ah[mf], bh[g][0], bh[g][1]);
                    mma16816(acc[mf][(p * 2 + g) * 2 + 1], ah[mf], bh[g][2], bh[g][3]);
                }
            // pass 2: Ah * Bl
            #pragma unroll
            for (int g = 0; g < 2; g++)
                #pragma unroll
                for (int mf = 0; mf < 2; mf++) {
                    mma16816(acc[mf][(p * 2 + g) * 2], ah[mf], bl[g][0], bl[g][1]);
                    mma16816(acc[mf][(p * 2 + g) * 2 + 1], ah[mf], bl[g][2], bl[g][3]);
                }
            // pass 3: Al * Bh
            #pragma unroll
            for (int g = 0; g < 2; g++)
                #pragma unroll
                for (int mf = 0; mf < 2; mf++) {
                    mma16816(acc[mf][(p * 2 + g) * 2], al[mf], bh[g][0], bh[g][1]);
                    mma16816(acc[mf][(p * 2 + g) * 2 + 1], al[mf], bh[g][2], bh[g][3]);
                }
        }
    }
}

// loader: identical to the validated 557us kernel
__device__ __forceinline__ void load_tile(u16* base, int tid, int kt, int m0,
                                          const u16* ah_src, const u16* al_src, int lda,
                                          const u16* bh_src, const u16* bl_src, int ldb,
                                          int bcol0) {
    #pragma unroll
    for (int i = 0; i < 2; i++) {
        int lin = tid * 2 + i;
        int ar = lin >> 2, ac = lin & 3;
        int gr = m0 + ar;
        bool v = gr < N_SITES;
        int grc = v ? gr : 0;
        const u16* sh_ = ah_src + (size_t)grc * lda + kt * 32 + ac * 8;
        const u16* sl_ = al_src + (size_t)grc * lda + kt * 32 + ac * 8;
        cpa16(base + ar * 40 + ac * 8, sh_, v);
        cpa16(base + SM_ALO + ar * 40 + ac * 8, sl_, v);
        int br = lin >> 4, bc = lin & 15;
        const u16* bh_ = bh_src + (size_t)(kt * 32 + br) * ldb + bcol0 + bc * 8;
        const u16* bl_ = bl_src + (size_t)(kt * 32 + br) * ldb + bcol0 + bc * 8;
        cpa16(base + SM_BHI + br * 136 + bc * 8, bh_, true);
        cpa16(base + SM_BLO + br * 136 + bc * 8, bl_, true);
    }
    cpa_commit();
}

// ---------------- GEMM1: xln @ w1 -> +b1, GELU, store h planes (staged), ssq ----------------
__global__ __launch_bounds__(256) void k_gemm1(const float* __restrict__ b1) {
    extern __shared__ u16 sm[];
    __shared__ float ssqs[128];
    int tid = threadIdx.x, lane = tid & 31, wid = tid >> 5;
    int mw = wid & 3, nw = wid >> 2;
    int nblk = blockIdx.x;           // 4 strips share A via L2
    int mt = blockIdx.y;
    int m0 = mt * 128;

    if (tid < 128) ssqs[tid] = 0.0f;

    float acc[2][8][4];
    #pragma unroll
    for (int i = 0; i < 2; i++)
        #pragma unroll
        for (int j = 0; j < 8; j++)
            #pragma unroll
            for (int r = 0; r < 4; r++) acc[i][j][r] = 0.f;

    load_tile(sm, tid, 0, m0, g_xh, g_xl, DIM, g_w1h, g_w1l, HID, nblk * 128);
    int stage = 0;
    #pragma unroll 1
    for (int kt = 0; kt < 4; kt++) {
        if (kt + 1 < 4) {
            load_tile(sm + (stage ^ 1) * SM_STAGE, tid, kt + 1, m0,
                      g_xh, g_xl, DIM, g_w1h, g_w1l, HID, nblk * 128);
            asm volatile("cp.async.wait_group 1;\n");
        } else {
            asm volatile("cp.async.wait_group 0;\n");
        }
        __syncthreads();
        mma_tile(sm + stage * SM_STAGE, lane, mw, nw, acc);
        __syncthreads();
        stage ^= 1;
    }

    // ---- epilogue: +b1, GELU, ssq; pack hi/lo pairs in-place into acc ----
    int colb = nw * 64 + (lane & 3) * 2;     // local col in 128-strip
    int colg = nblk * 128 + colb;            // global col
    float b1v[8][2];
    #pragma unroll
    for (int nf = 0; nf < 8; nf++) {
        b1v[nf][0] = b1[colg + nf * 8];
        b1v[nf][1] = b1[colg + nf * 8 + 1];
    }
    float ss[16];
    #pragma unroll
    for (int i = 0; i < 16; i++) ss[i] = 0.f;

    #pragma unroll
    for (int mf = 0; mf < 2; mf++) {
        #pragma unroll
        for (int half = 0; half < 2; half++) {
            bool rv = (m0 + mw * 32 + mf * 16 + half * 8 + (lane >> 2)) < N_SITES;
            #pragma unroll
            for (int nf = 0; nf < 8; nf++) {
                float v0 = gelu_exact(acc[mf][nf][half * 2] + b1v[nf][0]);
                float v1 = gelu_exact(acc[mf][nf][half * 2 + 1] + b1v[nf][1]);
                if (rv) {
                    ss[nf * 2] += v0 * v0;
                    ss[nf * 2 + 1] += v1 * v1;
                }
                u16 h0, l0, h1, l1;
                split_hl(v0, h0, l0);
                split_hl(v1, h1, l1);
                acc[mf][nf][half * 2] = __uint_as_float((u32)h0 | ((u32)h1 << 16));
                acc[mf][nf][half * 2 + 1] = __uint_as_float((u32)l0 | ((u32)l1 << 16));
            }
        }
    }
    #pragma unroll
    for (int nf = 0; nf < 8; nf++) {
        atomicAdd(&ssqs[colb + nf * 8], ss[nf * 2]);
        atomicAdd(&ssqs[colb + nf * 8 + 1], ss[nf * 2 + 1]);
    }

    // ---- staged coalesced store of hi then lo plane (128 rows x 64 u32, pad 68) ----
    u32* sp = (u32*)sm;
    int col32 = nw * 32 + (lane & 3);        // + nf*4
    #pragma unroll
    for (int plane = 0; plane < 2; plane++) {
        __syncthreads();
        #pragma unroll
        for (int mf = 0; mf < 2; mf++)
            #pragma unroll
            for (int half = 0; half < 2; half++) {
                int row = mw * 32 + mf * 16 + half * 8 + (lane >> 2);
                #pragma unroll
                for (int nf = 0; nf < 8; nf++)
                    sp[row * 68 + col32 + nf * 4] =
                        __float_as_uint(acc[mf][nf][half * 2 + plane]);
            }
        __syncthreads();
        u32* gdst = (u32*)(plane == 0 ? g_hh : g_hl);
        #pragma unroll
        for (int q = 0; q < 8; q++) {
            int idx = q * 1024 + tid * 4;
            int row = idx >> 6, col = idx & 63;
            int gr = m0 + row;
            if (gr < N_SITES) {
                uint4 v = *(uint4*)&sp[row * 68 + col];
                *(uint4*)(gdst + (size_t)gr * 256 + nblk * 64 + col) = v;
            }
        }
    }
    __syncthreads();
    if (tid < 128) atomicAdd(&g_ssq[nblk * 128 + tid], ssqs[tid]);
}

// ---------------- GRN scale ----------------
__global__ void k_grn(const float* __restrict__ grn_g) {
    __shared__ float sh[HID];
    int t = threadIdx.x;  // 512
    float gx = sqrtf(g_ssq[t]);
    sh[t] = gx;
    __syncthreads();
    for (int o = 256; o; o >>= 1) {
        if (t < o) sh[t] += sh[t + o];
        __syncthreads();
    }
    float nx = gx / (sh[0] * (1.0f / HID) + 1e-6f);
    g_scale[t] = 1.0f + grn_g[t] * nx;
}

// ---------------- GEMM2: (h*scale) @ w2 -> + c2 + residual (staged) ----------------
__global__ __launch_bounds__(256) void k_gemm2(const float* __restrict__ feats,
                                               float* __restrict__ out) {
    extern __shared__ u16 sm[];
    int tid = threadIdx.x, lane = tid & 31, wid = tid >> 5;
    int mw = wid & 3, nw = wid >> 2;
    int m0 = blockIdx.x * 128;

    float acc[2][8][4];
    #pragma unroll
    for (int i = 0; i < 2; i++)
        #pragma unroll
        for (int j = 0; j < 8; j++)
            #pragma unroll
            for (int r = 0; r < 4; r++) acc[i][j][r] = 0.f;

    load_tile(sm, tid, 0, m0, g_hh, g_hl, HID, g_w2h, g_w2l, DIM, 0);
    int stage = 0;
    #pragma unroll 1
    for (int kt = 0; kt < 16; kt++) {
        if (kt + 1 < 16) {
            load_tile(sm + (stage ^ 1) * SM_STAGE, tid, kt + 1, m0,
                      g_hh, g_hl, HID, g_w2h, g_w2l, DIM, 0);
            asm volatile("cp.async.wait_group 1;\n");
        } else {
            asm volatile("cp.async.wait_group 0;\n");
        }
        __syncthreads();
        mma_tile(sm + stage * SM_STAGE, lane, mw, nw, acc);
        __syncthreads();
        stage ^= 1;
    }

    // ---- epilogue: + c2, stage in smem (128 x 128 fp32, pad 132), coalesced out ----
    int colb = nw * 64 + (lane & 3) * 2;
    float c2v[8][2];
    #pragma unroll
    for (int nf = 0; nf < 8; nf++) {
        c2v[nf][0] = g_c2[colb + nf * 8];
        c2v[nf][1] = g_c2[colb + nf * 8 + 1];
    }
    float* spf = (float*)sm;
    #pragma unroll
    for (int mf = 0; mf < 2; mf++)
        #pragma unroll
        for (int half = 0; half < 2; half++) {
            int row = mw * 32 + mf * 16 + half * 8 + (lane >> 2);
            #pragma unroll
            for (int nf = 0; nf < 8; nf++) {
                int col = colb + nf * 8;
                spf[row * 132 + col] = acc[mf][nf][half * 2] + c2v[nf][0];
                spf[row * 132 + col + 1] = acc[mf][nf][half * 2 + 1] + c2v[nf][1];
            }
        }
    __syncthreads();
    #pragma unroll
    for (int q = 0; q < 16; q++) {
        int idx = q * 1024 + tid * 4;
        int row = idx >> 7, col = idx & 127;
        int gr = m0 + row;
        if (gr < N_SITES) {
            float4 fv = *(const float4*)(feats + (size_t)gr * DIM + col);
            float4 sv = *(float4*)&spf[row * 132 + col];
            sv.x += fv.x; sv.y += fv.y; sv.z += fv.z; sv.w += fv.w;
            *(float4*)(out + (size_t)gr * DIM + col) = sv;
        }
    }
}

// ---------------- launch ----------------
extern "C" void kernel_launch(void* const* d_in, const int* in_sizes, int n_in,
                              void* d_out, int out_size) {
    const float* feats = (const float*)d_in[0];
    const int*   nidx  = (const int*)d_in[1];
    const float* dww   = (const float*)d_in[2];
    const float* dwb   = (const float*)d_in[3];
    const float* lng   = (const float*)d_in[4];
    const float* lnb   = (const float*)d_in[5];
    const float* w1    = (const float*)d_in[6];
    const float* b1    = (const float*)d_in[7];
    const float* grng  = (const float*)d_in[8];
    const float* grnb  = (const float*)d_in[9];
    const float* w2    = (const float*)d_in[10];
    const float* b2    = (const float*)d_in[11];
    float* out = (float*)d_out;

    cudaFuncSetAttribute(k_gemm1, cudaFuncAttributeMaxDynamicSharedMemorySize, SMEM_BYTES);
    cudaFuncSetAttribute(k_gemm2, cudaFuncAttributeMaxDynamicSharedMemorySize, SMEM_BYTES);

    k_init<<<1, 512>>>(grnb, w2, b2);
    k_w1prep<<<128, 512>>>(w1);
    k_dwln<<<(N_SITES * 32 + 255) / 256, 256>>>(feats, nidx, dww, dwb, lng, lnb);
    dim3 g1(4, (N_SITES + 127) / 128);
    k_gemm1<<<g1, 256, SMEM_BYTES>>>(b1);
    k_grn<<<1, 512>>>(grng);
    k_w2prep<<<128, 512>>>(w2);
    k_gemm2<<<(N_SITES + 127) / 128, 256, SMEM_BYTES>>>(feats, out);
}

// round 12
// speedup vs baseline: 1.5632x; 1.5632x over previous
#include <cuda_runtime.h>
#include <cuda_bf16.h>
#include <cstdint>

#define N_SITES 100000
#define DIM 128
#define HID 512
#define KVOL 343

typedef unsigned short u16;
typedef unsigned int u32;

// ---------------- scratch (hi/lo bf16 planes) ----------------
__device__ __align__(16) u16 g_xh[(size_t)N_SITES * DIM];
__device__ __align__(16) u16 g_xl[(size_t)N_SITES * DIM];
__device__ __align__(16) u16 g_hh[(size_t)N_SITES * HID];
__device__ __align__(16) u16 g_hl[(size_t)N_SITES * HID];
__device__ __align__(16) u16 g_w1h[DIM * HID];   // [k][n]
__device__ __align__(16) u16 g_w1l[DIM * HID];
__device__ __align__(16) u16 g_w2h[HID * DIM];   // [k][n], pre-scaled by GRN
__device__ __align__(16) u16 g_w2l[HID * DIM];
__device__ float g_ssq[HID];
__device__ float g_scale[HID];
__device__ float g_c2[DIM];

// ---------------- helpers ----------------
__device__ __forceinline__ void split_hl(float f, u16& h, u16& l) {
    __nv_bfloat16 hb = __float2bfloat16(f);
    h = __bfloat16_as_ushort(hb);
    l = __bfloat16_as_ushort(__float2bfloat16(f - __bfloat162float(hb)));
}
__device__ __forceinline__ float gelu_exact(float x) {
    return 0.5f * x * (1.0f + erff(x * 0.7071067811865475f));
}
// A&S 7.1.26 erf: |abs err| <= 1.5e-7 — far below our 3.7e-6 rel_err budget
__device__ __forceinline__ float gelu_fast(float x) {
    float u = 0.70710678118f * x;
    float a = fabsf(u);
    float s = __fdividef(1.0f, fmaf(0.3275911f, a, 1.0f));
    float y = fmaf(fmaf(fmaf(fmaf(1.061405429f, s, -1.453152027f), s, 1.421413741f),
                        s, -0.284496736f), s, 0.254829592f);
    y *= s;
    float e = __expf(-a * a);
    float erfa = fmaf(-y, e, 1.0f);          // erf(|u|)
    float erfu = copysignf(erfa, u);
    return 0.5f * x * (1.0f + erfu);
}
__device__ __forceinline__ void ldsm4(uint32_t r[4], const void* p) {
    uint32_t a = (uint32_t)__cvta_generic_to_shared(p);
    asm volatile("ldmatrix.sync.aligned.m8n8.x4.shared.b16 {%0,%1,%2,%3}, [%4];"
                 : "=r"(r[0]), "=r"(r[1]), "=r"(r[2]), "=r"(r[3]) : "r"(a));
}
__device__ __forceinline__ void ldsm4t(uint32_t r[4], const void* p) {
    uint32_t a = (uint32_t)__cvta_generic_to_shared(p);
    asm volatile("ldmatrix.sync.aligned.m8n8.x4.trans.shared.b16 {%0,%1,%2,%3}, [%4];"
                 : "=r"(r[0]), "=r"(r[1]), "=r"(r[2]), "=r"(r[3]) : "r"(a));
}
__device__ __forceinline__ void mma16816(float c[4], const uint32_t a[4],
                                         uint32_t b0, uint32_t b1) {
    asm volatile(
        "mma.sync.aligned.m16n8k16.row.col.f32.bf16.bf16.f32 "
        "{%0,%1,%2,%3},{%4,%5,%6,%7},{%8,%9},{%0,%1,%2,%3};"
        : "+f"(c[0]), "+f"(c[1]), "+f"(c[2]), "+f"(c[3])
        : "r"(a[0]), "r"(a[1]), "r"(a[2]), "r"(a[3]), "r"(b0), "r"(b1));
}
__device__ __forceinline__ void cpa16(u16* dst, const u16* src, bool valid) {
    uint32_t d = (uint32_t)__cvta_generic_to_shared(dst);
    int sz = valid ? 16 : 0;
    asm volatile("cp.async.cg.shared.global [%0], [%1], 16, %2;\n"
                 :: "r"(d), "l"(src), "r"(sz));
}
__device__ __forceinline__ void cpa_commit() {
    asm volatile("cp.async.commit_group;\n");
}

// ---------------- init: zero ssq + c2 = b2 + grn_b @ w2 ----------------
__global__ void k_init(const float* __restrict__ grn_b, const float* __restrict__ w2,
                       const float* __restrict__ b2) {
    __shared__ float part[4][DIM];
    int t = threadIdx.x;  // 512
    g_ssq[t] = 0.0f;
    int jg = t >> 7, col = t & 127;
    float s = 0.f;
    #pragma unroll 4
    for (int j = jg * 128; j < jg * 128 + 128; j++)
        s = fmaf(grn_b[j], w2[(size_t)j * DIM + col], s);
    part[jg][col] = s;
    __syncthreads();
    if (t < DIM) g_c2[t] = b2[t] + part[0][t] + part[1][t] + part[2][t] + part[3][t];
}

// ---------------- prep: split w1 into hi/lo planes [k][n] ----------------
__global__ void k_w1prep(const float* __restrict__ w1) {
    int idx = blockIdx.x * 512 + threadIdx.x;  // 128 x 512
    float f = w1[idx];
    u16 h, l;
    split_hl(f, h, l);
    g_w1h[idx] = h;
    g_w1l[idx] = l;
}

// ---------------- prep: split (scale[k] * w2) into hi/lo planes [k][n] ----------------
__global__ void k_w2prep(const float* __restrict__ w2) {
    int idx = blockIdx.x * 512 + threadIdx.x;  // grid 128, k = idx>>7
    int k = idx >> 7;
    float f = g_scale[k] * w2[idx];
    u16 h, l;
    split_hl(f, h, l);
    g_w2h[idx] = h;
    g_w2l[idx] = l;
}

// ---------------- kernel 1: sparse depthwise conv + LayerNorm -> hi/lo planes ----------------
__global__ __launch_bounds__(256) void k_dwln(
    const float* __restrict__ feats, const int* __restrict__ nidx,
    const float* __restrict__ dww, const float* __restrict__ dwb,
    const float* __restrict__ lng, const float* __restrict__ lnb) {
    int warp = (blockIdx.x * blockDim.x + threadIdx.x) >> 5;
    int lane = threadIdx.x & 31;
    if (warp >= N_SITES) return;

    const int* nb = nidx + (size_t)warp * KVOL;
    float4 acc = make_float4(0.f, 0.f, 0.f, 0.f);

    #pragma unroll 1
    for (int base = 0; base < KVOL; base += 32) {
        int k = base + lane;
        int idx = (k < KVOL) ? __ldg(nb + k) : N_SITES;
        unsigned m = __ballot_sync(0xffffffffu, idx < N_SITES);
        while (m) {
            int b = __ffs(m) - 1;
            m &= m - 1;
            int id = __shfl_sync(0xffffffffu, idx, b);
            int kk = base + b;
            float4 f = *(const float4*)(feats + (size_t)id * DIM + lane * 4);
            float4 w = *(const float4*)(dww + (size_t)kk * DIM + lane * 4);
            acc.x = fmaf(f.x, w.x, acc.x);
            acc.y = fmaf(f.y, w.y, acc.y);
            acc.z = fmaf(f.z, w.z, acc.z);
            acc.w = fmaf(f.w, w.w, acc.w);
        }
    }
    float4 bb = *(const float4*)(dwb + lane * 4);
    acc.x += bb.x; acc.y += bb.y; acc.z += bb.z; acc.w += bb.w;

    float s = acc.x + acc.y + acc.z + acc.w;
    float q = acc.x * acc.x + acc.y * acc.y + acc.z * acc.z + acc.w * acc.w;
    #pragma unroll
    for (int o = 16; o; o >>= 1) {
        s += __shfl_xor_sync(0xffffffffu, s, o);
        q += __shfl_xor_sync(0xffffffffu, q, o);
    }
    float mu = s * (1.0f / DIM);
    float var = q * (1.0f / DIM) - mu * mu;
    float rs = rsqrtf(var + 1e-6f);

    float4 g = *(const float4*)(lng + lane * 4);
    float4 be = *(const float4*)(lnb + lane * 4);
    float o0 = (acc.x - mu) * rs * g.x + be.x;
    float o1 = (acc.y - mu) * rs * g.y + be.y;
    float o2 = (acc.z - mu) * rs * g.z + be.z;
    float o3 = (acc.w - mu) * rs * g.w + be.w;
    u16 h0, l0, h1, l1, h2, l2, h3, l3;
    split_hl(o0, h0, l0); split_hl(o1, h1, l1);
    split_hl(o2, h2, l2); split_hl(o3, h3, l3);
    size_t off = (size_t)warp * DIM + lane * 4;
    *(uint2*)(g_xh + off) = make_uint2((u32)h0 | ((u32)h1 << 16), (u32)h2 | ((u32)h3 << 16));
    *(uint2*)(g_xl + off) = make_uint2((u32)l0 | ((u32)l1 << 16), (u32)l2 | ((u32)l3 << 16));
}

// ---------------- GEMM common: 128x128 tile, BK=32, 256 thr, 2-stage cp.async ----------------
// smem layout (u16 units per stage): A_hi@0 (128x40), A_lo@5120, B_hi@10240 (32x136), B_lo@14592
#define SM_ALO 5120
#define SM_BHI 10240
#define SM_BLO 14592
#define SM_STAGE 18944
#define SMEM_BYTES (2 * SM_STAGE * 2)

// R5 ordering (validated fastest: 283us GEMM1)
__device__ __forceinline__ void mma_tile(const u16* base, int lane, int mw, int nw,
                                         float acc[2][8][4]) {
    #pragma unroll
    for (int ks = 0; ks < 2; ks++) {
        uint32_t ah[2][4], al[2][4];
        #pragma unroll
        for (int mf = 0; mf < 2; mf++) {
            int arow = mw * 32 + mf * 16 + (lane & 15);
            int acol = ks * 16 + 8 * (lane >> 4);
            ldsm4(ah[mf], base + arow * 40 + acol);
            ldsm4(al[mf], base + SM_ALO + arow * 40 + acol);
        }
        #pragma unroll
        for (int ng = 0; ng < 4; ng++) {
            uint32_t bh[4], bl[4];
            int brow = ks * 16 + (lane & 15);
            int bcol = nw * 64 + ng * 16 + 8 * (lane >> 4);
            ldsm4t(bh, base + SM_BHI + brow * 136 + bcol);
            ldsm4t(bl, base + SM_BLO + brow * 136 + bcol);
            #pragma unroll
            for (int mf = 0; mf < 2; mf++) {
                mma16816(acc[mf][ng * 2], ah[mf], bh[0], bh[1]);
                mma16816(acc[mf][ng * 2], ah[mf], bl[0], bl[1]);
                mma16816(acc[mf][ng * 2], al[mf], bh[0], bh[1]);
                mma16816(acc[mf][ng * 2 + 1], ah[mf], bh[2], bh[3]);
                mma16816(acc[mf][ng * 2 + 1], ah[mf], bl[2], bl[3]);
                mma16816(acc[mf][ng * 2 + 1], al[mf], bh[2], bh[3]);
            }
        }
    }
}

// loader: identical to the validated 557us kernel
__device__ __forceinline__ void load_tile(u16* base, int tid, int kt, int m0,
                                          const u16* ah_src, const u16* al_src, int lda,
                                          const u16* bh_src, const u16* bl_src, int ldb,
                                          int bcol0) {
    #pragma unroll
    for (int i = 0; i < 2; i++) {
        int lin = tid * 2 + i;
        int ar = lin >> 2, ac = lin & 3;
        int gr = m0 + ar;
        bool v = gr < N_SITES;
        int grc = v ? gr : 0;
        const u16* sh_ = ah_src + (size_t)grc * lda + kt * 32 + ac * 8;
        const u16* sl_ = al_src + (size_t)grc * lda + kt * 32 + ac * 8;
        cpa16(base + ar * 40 + ac * 8, sh_, v);
        cpa16(base + SM_ALO + ar * 40 + ac * 8, sl_, v);
        int br = lin >> 4, bc = lin & 15;
        const u16* bh_ = bh_src + (size_t)(kt * 32 + br) * ldb + bcol0 + bc * 8;
        const u16* bl_ = bl_src + (size_t)(kt * 32 + br) * ldb + bcol0 + bc * 8;
        cpa16(base + SM_BHI + br * 136 + bc * 8, bh_, true);
        cpa16(base + SM_BLO + br * 136 + bc * 8, bl_, true);
    }
    cpa_commit();
}

// ---------------- GEMM1: xln @ w1 -> +b1, GELU, store h planes (staged), ssq ----------------
__global__ __launch_bounds__(256) void k_gemm1(const float* __restrict__ b1) {
    extern __shared__ u16 sm[];
    __shared__ float ssqs[128];
    int tid = threadIdx.x, lane = tid & 31, wid = tid >> 5;
    int mw = wid & 3, nw = wid >> 2;
    int nblk = blockIdx.x;           // 4 strips share A via L2
    int mt = blockIdx.y;
    int m0 = mt * 128;

    if (tid < 128) ssqs[tid] = 0.0f;

    float acc[2][8][4];
    #pragma unroll
    for (int i = 0; i < 2; i++)
        #pragma unroll
        for (int j = 0; j < 8; j++)
            #pragma unroll
            for (int r = 0; r < 4; r++) acc[i][j][r] = 0.f;

    load_tile(sm, tid, 0, m0, g_xh, g_xl, DIM, g_w1h, g_w1l, HID, nblk * 128);
    int stage = 0;
    #pragma unroll 1
    for (int kt = 0; kt < 4; kt++) {
        if (kt + 1 < 4) {
            load_tile(sm + (stage ^ 1) * SM_STAGE, tid, kt + 1, m0,
                      g_xh, g_xl, DIM, g_w1h, g_w1l, HID, nblk * 128);
            asm volatile("cp.async.wait_group 1;\n");
        } else {
            asm volatile("cp.async.wait_group 0;\n");
        }
        __syncthreads();
        mma_tile(sm + stage * SM_STAGE, lane, mw, nw, acc);
        __syncthreads();
        stage ^= 1;
    }

    // ---- epilogue: +b1, fast GELU, ssq; pack hi/lo pairs in-place into acc ----
    int colb = nw * 64 + (lane & 3) * 2;     // local col in 128-strip
    int colg = nblk * 128 + colb;            // global col
    float b1v[8][2];
    #pragma unroll
    for (int nf = 0; nf < 8; nf++) {
        b1v[nf][0] = b1[colg + nf * 8];
        b1v[nf][1] = b1[colg + nf * 8 + 1];
    }
    float ss[16];
    #pragma unroll
    for (int i = 0; i < 16; i++) ss[i] = 0.f;

    #pragma unroll
    for (int mf = 0; mf < 2; mf++) {
        #pragma unroll
        for (int half = 0; half < 2; half++) {
            bool rv = (m0 + mw * 32 + mf * 16 + half * 8 + (lane >> 2)) < N_SITES;
            #pragma unroll
            for (int nf = 0; nf < 8; nf++) {
                float v0 = gelu_fast(acc[mf][nf][half * 2] + b1v[nf][0]);
                float v1 = gelu_fast(acc[mf][nf][half * 2 + 1] + b1v[nf][1]);
                if (rv) {
                    ss[nf * 2] += v0 * v0;
                    ss[nf * 2 + 1] += v1 * v1;
                }
                u16 h0, l0, h1, l1;
                split_hl(v0, h0, l0);
                split_hl(v1, h1, l1);
                acc[mf][nf][half * 2] = __uint_as_float((u32)h0 | ((u32)h1 << 16));
                acc[mf][nf][half * 2 + 1] = __uint_as_float((u32)l0 | ((u32)l1 << 16));
            }
        }
    }
    #pragma unroll
    for (int nf = 0; nf < 8; nf++) {
        atomicAdd(&ssqs[colb + nf * 8], ss[nf * 2]);
        atomicAdd(&ssqs[colb + nf * 8 + 1], ss[nf * 2 + 1]);
    }

    // ---- staged coalesced store of hi then lo plane (128 rows x 64 u32, pad 68) ----
    u32* sp = (u32*)sm;
    int col32 = nw * 32 + (lane & 3);        // + nf*4
    #pragma unroll
    for (int plane = 0; plane < 2; plane++) {
        __syncthreads();
        #pragma unroll
        for (int mf = 0; mf < 2; mf++)
            #pragma unroll
            for (int half = 0; half < 2; half++) {
                int row = mw * 32 + mf * 16 + half * 8 + (lane >> 2);
                #pragma unroll
                for (int nf = 0; nf < 8; nf++)
                    sp[row * 68 + col32 + nf * 4] =
                        __float_as_uint(acc[mf][nf][half * 2 + plane]);
            }
        __syncthreads();
        u32* gdst = (u32*)(plane == 0 ? g_hh : g_hl);
        #pragma unroll
        for (int q = 0; q < 8; q++) {
            int idx = q * 1024 + tid * 4;
            int row = idx >> 6, col = idx & 63;
            int gr = m0 + row;
            if (gr < N_SITES) {
                uint4 v = *(uint4*)&sp[row * 68 + col];
                *(uint4*)(gdst + (size_t)gr * 256 + nblk * 64 + col) = v;
            }
        }
    }
    __syncthreads();
    if (tid < 128) atomicAdd(&g_ssq[nblk * 128 + tid], ssqs[tid]);
}

// ---------------- GRN scale ----------------
__global__ void k_grn(const float* __restrict__ grn_g) {
    __shared__ float sh[HID];
    int t = threadIdx.x;  // 512
    float gx = sqrtf(g_ssq[t]);
    sh[t] = gx;
    __syncthreads();
    for (int o = 256; o; o >>= 1) {
        if (t < o) sh[t] += sh[t + o];
        __syncthreads();
    }
    float nx = gx / (sh[0] * (1.0f / HID) + 1e-6f);
    g_scale[t] = 1.0f + grn_g[t] * nx;
}

// ---------------- GEMM2: (h*scale) @ w2 -> + c2 + residual (staged) ----------------
__global__ __launch_bounds__(256) void k_gemm2(const float* __restrict__ feats,
                                               float* __restrict__ out) {
    extern __shared__ u16 sm[];
    int tid = threadIdx.x, lane = tid & 31, wid = tid >> 5;
    int mw = wid & 3, nw = wid >> 2;
    int m0 = blockIdx.x * 128;

    float acc[2][8][4];
    #pragma unroll
    for (int i = 0; i < 2; i++)
        #pragma unroll
        for (int j = 0; j < 8; j++)
            #pragma unroll
            for (int r = 0; r < 4; r++) acc[i][j][r] = 0.f;

    load_tile(sm, tid, 0, m0, g_hh, g_hl, HID, g_w2h, g_w2l, DIM, 0);
    int stage = 0;
    #pragma unroll 1
    for (int kt = 0; kt < 16; kt++) {
        if (kt + 1 < 16) {
            load_tile(sm + (stage ^ 1) * SM_STAGE, tid, kt + 1, m0,
                      g_hh, g_hl, HID, g_w2h, g_w2l, DIM, 0);
            asm volatile("cp.async.wait_group 1;\n");
        } else {
            asm volatile("cp.async.wait_group 0;\n");
        }
        __syncthreads();
        mma_tile(sm + stage * SM_STAGE, lane, mw, nw, acc);
        __syncthreads();
        stage ^= 1;
    }

    // ---- epilogue: + c2, stage in smem (128 x 128 fp32, pad 132), coalesced out ----
    int colb = nw * 64 + (lane & 3) * 2;
    float c2v[8][2];
    #pragma unroll
    for (int nf = 0; nf < 8; nf++) {
        c2v[nf][0] = g_c2[colb + nf * 8];
        c2v[nf][1] = g_c2[colb + nf * 8 + 1];
    }
    float* spf = (float*)sm;
    #pragma unroll
    for (int mf = 0; mf < 2; mf++)
        #pragma unroll
        for (int half = 0; half < 2; half++) {
            int row = mw * 32 + mf * 16 + half * 8 + (lane >> 2);
            #pragma unroll
            for (int nf = 0; nf < 8; nf++) {
                int col = colb + nf * 8;
                spf[row * 132 + col] = acc[mf][nf][half * 2] + c2v[nf][0];
                spf[row * 132 + col + 1] = acc[mf][nf][half * 2 + 1] + c2v[nf][1];
            }
        }
    __syncthreads();
    #pragma unroll
    for (int q = 0; q < 16; q++) {
        int idx = q * 1024 + tid * 4;
        int row = idx >> 7, col = idx & 127;
        int gr = m0 + row;
        if (gr < N_SITES) {
            float4 fv = *(const float4*)(feats + (size_t)gr * DIM + col);
            float4 sv = *(float4*)&spf[row * 132 + col];
            sv.x += fv.x; sv.y += fv.y; sv.z += fv.z; sv.w += fv.w;
            *(float4*)(out + (size_t)gr * DIM + col) = sv;
        }
    }
}

// ---------------- launch ----------------
extern "C" void kernel_launch(void* const* d_in, const int* in_sizes, int n_in,
                              void* d_out, int out_size) {
    const float* feats = (const float*)d_in[0];
    const int*   nidx  = (const int*)d_in[1];
    const float* dww   = (const float*)d_in[2];
    const float* dwb   = (const float*)d_in[3];
    const float* lng   = (const float*)d_in[4];
    const float* lnb   = (const float*)d_in[5];
    const float* w1    = (const float*)d_in[6];
    const float* b1    = (const float*)d_in[7];
    const float* grng  = (const float*)d_in[8];
    const float* grnb  = (const float*)d_in[9];
    const float* w2    = (const float*)d_in[10];
    const float* b2    = (const float*)d_in[11];
    float* out = (float*)d_out;

    cudaFuncSetAttribute(k_gemm1, cudaFuncAttributeMaxDynamicSharedMemorySize, SMEM_BYTES);
    cudaFuncSetAttribute(k_gemm2, cudaFuncAttributeMaxDynamicSharedMemorySize, SMEM_BYTES);

    k_init<<<1, 512>>>(grnb, w2, b2);
    k_w1prep<<<128, 512>>>(w1);
    k_dwln<<<(N_SITES * 32 + 255) / 256, 256>>>(feats, nidx, dww, dwb, lng, lnb);
    dim3 g1(4, (N_SITES + 127) / 128);
    k_gemm1<<<g1, 256, SMEM_BYTES>>>(b1);
    k_grn<<<1, 512>>>(grng);
    k_w2prep<<<128, 512>>>(w2);
    k_gemm2<<<(N_SITES + 127) / 128, 256, SMEM_BYTES>>>(feats, out);
}

// round 17
// speedup vs baseline: 1.7320x; 1.1080x over previous
#include <cuda_runtime.h>
#include <cuda_fp16.h>
#include <cstdint>

#define N_SITES 100000
#define DIM 128
#define HID 512
#define KVOL 343

typedef unsigned short u16;
typedef unsigned int u32;

// ---------------- scratch (fp16 planes: A operands hi/lo, weights single) ----------------
__device__ __align__(16) u16 g_xh[(size_t)N_SITES * DIM];
__device__ __align__(16) u16 g_xl[(size_t)N_SITES * DIM];
__device__ __align__(16) u16 g_hh[(size_t)N_SITES * HID];
__device__ __align__(16) u16 g_hl[(size_t)N_SITES * HID];
__device__ __align__(16) u16 g_w1[DIM * HID];    // [k][n] fp16
__device__ __align__(16) u16 g_w2[HID * DIM];    // [k][n] fp16, pre-scaled by GRN
__device__ float g_ssq[HID];
__device__ float g_scale[HID];
__device__ float g_c2[DIM];

// ---------------- helpers ----------------
__device__ __forceinline__ void split_hl16(float f, u16& h, u16& l) {
    __half hb = __float2half_rn(f);
    h = __half_as_ushort(hb);
    l = __half_as_ushort(__float2half_rn(f - __half2float(hb)));
}
// A&S 7.1.26 erf: |abs err| <= 1.5e-7
__device__ __forceinline__ float gelu_fast(float x) {
    float u = 0.70710678118f * x;
    float a = fabsf(u);
    float s = __fdividef(1.0f, fmaf(0.3275911f, a, 1.0f));
    float y = fmaf(fmaf(fmaf(fmaf(1.061405429f, s, -1.453152027f), s, 1.421413741f),
                        s, -0.284496736f), s, 0.254829592f);
    y *= s;
    float e = __expf(-a * a);
    float erfa = fmaf(-y, e, 1.0f);
    float erfu = copysignf(erfa, u);
    return 0.5f * x * (1.0f + erfu);
}
__device__ __forceinline__ void ldsm4(uint32_t r[4], const void* p) {
    uint32_t a = (uint32_t)__cvta_generic_to_shared(p);
    asm volatile("ldmatrix.sync.aligned.m8n8.x4.shared.b16 {%0,%1,%2,%3}, [%4];"
                 : "=r"(r[0]), "=r"(r[1]), "=r"(r[2]), "=r"(r[3]) : "r"(a));
}
__device__ __forceinline__ void ldsm4t(uint32_t r[4], const void* p) {
    uint32_t a = (uint32_t)__cvta_generic_to_shared(p);
    asm volatile("ldmatrix.sync.aligned.m8n8.x4.trans.shared.b16 {%0,%1,%2,%3}, [%4];"
                 : "=r"(r[0]), "=r"(r[1]), "=r"(r[2]), "=r"(r[3]) : "r"(a));
}
__device__ __forceinline__ void mma16816(float c[4], const uint32_t a[4],
                                         uint32_t b0, uint32_t b1) {
    asm volatile(
        "mma.sync.aligned.m16n8k16.row.col.f32.f16.f16.f32 "
        "{%0,%1,%2,%3},{%4,%5,%6,%7},{%8,%9},{%0,%1,%2,%3};"
        : "+f"(c[0]), "+f"(c[1]), "+f"(c[2]), "+f"(c[3])
        : "r"(a[0]), "r"(a[1]), "r"(a[2]), "r"(a[3]), "r"(b0), "r"(b1));
}
__device__ __forceinline__ void cpa16(u16* dst, const u16* src, bool valid) {
    uint32_t d = (uint32_t)__cvta_generic_to_shared(dst);
    int sz = valid ? 16 : 0;
    asm volatile("cp.async.cg.shared.global [%0], [%1], 16, %2;\n"
                 :: "r"(d), "l"(src), "r"(sz));
}
__device__ __forceinline__ void cpa_commit() {
    asm volatile("cp.async.commit_group;\n");
}

// ---------------- init: zero ssq + c2 = b2 + grn_b @ w2 ----------------
__global__ void k_init(const float* __restrict__ grn_b, const float* __restrict__ w2,
                       const float* __restrict__ b2) {
    __shared__ float part[4][DIM];
    int t = threadIdx.x;  // 512
    g_ssq[t] = 0.0f;
    int jg = t >> 7, col = t & 127;
    float s = 0.f;
    #pragma unroll 4
    for (int j = jg * 128; j < jg * 128 + 128; j++)
        s = fmaf(grn_b[j], w2[(size_t)j * DIM + col], s);
    part[jg][col] = s;
    __syncthreads();
    if (t < DIM) g_c2[t] = b2[t] + part[0][t] + part[1][t] + part[2][t] + part[3][t];
}

// ---------------- prep: w1 -> fp16 plane [k][n] ----------------
__global__ void k_w1prep(const float* __restrict__ w1) {
    int idx = blockIdx.x * 512 + threadIdx.x;  // 128 x 512
    g_w1[idx] = __half_as_ushort(__float2half_rn(w1[idx]));
}

// ---------------- prep: (scale[k] * w2) -> fp16 plane [k][n] ----------------
__global__ void k_w2prep(const float* __restrict__ w2) {
    int idx = blockIdx.x * 512 + threadIdx.x;  // grid 128, k = idx>>7
    int k = idx >> 7;
    g_w2[idx] = __half_as_ushort(__float2half_rn(g_scale[k] * w2[idx]));
}

// ---------------- kernel 1: sparse depthwise conv + LayerNorm -> fp16 hi/lo planes ----------------
__global__ __launch_bounds__(256) void k_dwln(
    const float* __restrict__ feats, const int* __restrict__ nidx,
    const float* __restrict__ dww, const float* __restrict__ dwb,
    const float* __restrict__ lng, const float* __restrict__ lnb) {
    int warp = (blockIdx.x * blockDim.x + threadIdx.x) >> 5;
    int lane = threadIdx.x & 31;
    if (warp >= N_SITES) return;

    const int* nb = nidx + (size_t)warp * KVOL;
    float4 acc = make_float4(0.f, 0.f, 0.f, 0.f);

    #pragma unroll 1
    for (int base = 0; base < KVOL; base += 32) {
        int k = base + lane;
        int idx = (k < KVOL) ? __ldg(nb + k) : N_SITES;
        unsigned m = __ballot_sync(0xffffffffu, idx < N_SITES);
        while (m) {
            int b = __ffs(m) - 1;
            m &= m - 1;
            int id = __shfl_sync(0xffffffffu, idx, b);
            int kk = base + b;
            float4 f = *(const float4*)(feats + (size_t)id * DIM + lane * 4);
            float4 w = *(const float4*)(dww + (size_t)kk * DIM + lane * 4);
            acc.x = fmaf(f.x, w.x, acc.x);
            acc.y = fmaf(f.y, w.y, acc.y);
            acc.z = fmaf(f.z, w.z, acc.z);
            acc.w = fmaf(f.w, w.w, acc.w);
        }
    }
    float4 bb = *(const float4*)(dwb + lane * 4);
    acc.x += bb.x; acc.y += bb.y; acc.z += bb.z; acc.w += bb.w;

    float s = acc.x + acc.y + acc.z + acc.w;
    float q = acc.x * acc.x + acc.y * acc.y + acc.z * acc.z + acc.w * acc.w;
    #pragma unroll
    for (int o = 16; o; o >>= 1) {
        s += __shfl_xor_sync(0xffffffffu, s, o);
        q += __shfl_xor_sync(0xffffffffu, q, o);
    }
    float mu = s * (1.0f / DIM);
    float var = q * (1.0f / DIM) - mu * mu;
    float rs = rsqrtf(var + 1e-6f);

    float4 g = *(const float4*)(lng + lane * 4);
    float4 be = *(const float4*)(lnb + lane * 4);
    float o0 = (acc.x - mu) * rs * g.x + be.x;
    float o1 = (acc.y - mu) * rs * g.y + be.y;
    float o2 = (acc.z - mu) * rs * g.z + be.z;
    float o3 = (acc.w - mu) * rs * g.w + be.w;
    u16 h0, l0, h1, l1, h2, l2, h3, l3;
    split_hl16(o0, h0, l0); split_hl16(o1, h1, l1);
    split_hl16(o2, h2, l2); split_hl16(o3, h3, l3);
    size_t off = (size_t)warp * DIM + lane * 4;
    *(uint2*)(g_xh + off) = make_uint2((u32)h0 | ((u32)h1 << 16), (u32)h2 | ((u32)h3 << 16));
    *(uint2*)(g_xl + off) = make_uint2((u32)l0 | ((u32)l1 << 16), (u32)l2 | ((u32)l3 << 16));
}

// ---------------- GEMM common: 128x128 tile, BK=32, 256 thr, 2-stage cp.async ----------------
// smem (u16 units/stage): A_hi@0 (128x40=5120), A_lo@5120, B@10240 (32x136=4352)
#define SM_ALO 5120
#define SM_B 10240
#define SM_STAGE 14592
#define SMEM1_BYTES (2 * SM_STAGE * 2)          // 58368
#define SMEM2_BYTES 67584                        // max(2*stage, 128*132*4 out staging)

// 2-pass fp16 MMA, R5-style ordering
__device__ __forceinline__ void mma_tile(const u16* base, int lane, int mw, int nw,
                                         float acc[2][8][4]) {
    #pragma unroll
    for (int ks = 0; ks < 2; ks++) {
        uint32_t ah[2][4], al[2][4];
        #pragma unroll
        for (int mf = 0; mf < 2; mf++) {
            int arow = mw * 32 + mf * 16 + (lane & 15);
            int acol = ks * 16 + 8 * (lane >> 4);
            ldsm4(ah[mf], base + arow * 40 + acol);
            ldsm4(al[mf], base + SM_ALO + arow * 40 + acol);
        }
        #pragma unroll
        for (int ng = 0; ng < 4; ng++) {
            uint32_t bf[4];
            int brow = ks * 16 + (lane & 15);
            int bcol = nw * 64 + ng * 16 + 8 * (lane >> 4);
            ldsm4t(bf, base + SM_B + brow * 136 + bcol);
            #pragma unroll
            for (int mf = 0; mf < 2; mf++) {
                mma16816(acc[mf][ng * 2], ah[mf], bf[0], bf[1]);
                mma16816(acc[mf][ng * 2], al[mf], bf[0], bf[1]);
                mma16816(acc[mf][ng * 2 + 1], ah[mf], bf[2], bf[3]);
                mma16816(acc[mf][ng * 2 + 1], al[mf], bf[2], bf[3]);
            }
        }
    }
}

__device__ __forceinline__ void load_tile(u16* base, int tid, int kt, int m0,
                                          const u16* ah_src, const u16* al_src, int lda,
                                          const u16* b_src, int ldb, int bcol0) {
    #pragma unroll
    for (int i = 0; i < 2; i++) {
        int lin = tid * 2 + i;
        int ar = lin >> 2, ac = lin & 3;
        int gr = m0 + ar;
        bool v = gr < N_SITES;
        int grc = v ? gr : 0;
        const u16* sh_ = ah_src + (size_t)grc * lda + kt * 32 + ac * 8;
        const u16* sl_ = al_src + (size_t)grc * lda + kt * 32 + ac * 8;
        cpa16(base + ar * 40 + ac * 8, sh_, v);
        cpa16(base + SM_ALO + ar * 40 + ac * 8, sl_, v);
        int br = lin >> 4, bc = lin & 15;
        const u16* b_ = b_src + (size_t)(kt * 32 + br) * ldb + bcol0 + bc * 8;
        cpa16(base + SM_B + br * 136 + bc * 8, b_, true);
    }
    cpa_commit();
}

// ---------------- GEMM1: xln @ w1 -> +b1, GELU, store h planes (staged), ssq ----------------
__global__ __launch_bounds__(256) void k_gemm1(const float* __restrict__ b1) {
    extern __shared__ u16 sm[];
    __shared__ float ssqs[128];
    int tid = threadIdx.x, lane = tid & 31, wid = tid >> 5;
    int mw = wid & 3, nw = wid >> 2;
    int nblk = blockIdx.x;           // 4 strips share A via L2
    int mt = blockIdx.y;
    int m0 = mt * 128;

    if (tid < 128) ssqs[tid] = 0.0f;

    float acc[2][8][4];
    #pragma unroll
    for (int i = 0; i < 2; i++)
        #pragma unroll
        for (int j = 0; j < 8; j++)
            #pragma unroll
            for (int r = 0; r < 4; r++) acc[i][j][r] = 0.f;

    load_tile(sm, tid, 0, m0, g_xh, g_xl, DIM, g_w1, HID, nblk * 128);
    int stage = 0;
    #pragma unroll 1
    for (int kt = 0; kt < 4; kt++) {
        if (kt + 1 < 4) {
            load_tile(sm + (stage ^ 1) * SM_STAGE, tid, kt + 1, m0,
                      g_xh, g_xl, DIM, g_w1, HID, nblk * 128);
            asm volatile("cp.async.wait_group 1;\n");
        } else {
            asm volatile("cp.async.wait_group 0;\n");
        }
        __syncthreads();
        mma_tile(sm + stage * SM_STAGE, lane, mw, nw, acc);
        __syncthreads();
        stage ^= 1;
    }

    // ---- epilogue: +b1, fast GELU, ssq; pack fp16 hi/lo pairs in-place into acc ----
    int colb = nw * 64 + (lane & 3) * 2;
    int colg = nblk * 128 + colb;
    float b1v[8][2];
    #pragma unroll
    for (int nf = 0; nf < 8; nf++) {
        b1v[nf][0] = b1[colg + nf * 8];
        b1v[nf][1] = b1[colg + nf * 8 + 1];
    }
    float ss[16];
    #pragma unroll
    for (int i = 0; i < 16; i++) ss[i] = 0.f;

    #pragma unroll
    for (int mf = 0; mf < 2; mf++) {
        #pragma unroll
        for (int half = 0; half < 2; half++) {
            bool rv = (m0 + mw * 32 + mf * 16 + half * 8 + (lane >> 2)) < N_SITES;
            #pragma unroll
            for (int nf = 0; nf < 8; nf++) {
                float v0 = gelu_fast(acc[mf][nf][half * 2] + b1v[nf][0]);
                float v1 = gelu_fast(acc[mf][nf][half * 2 + 1] + b1v[nf][1]);
                if (rv) {
                    ss[nf * 2] += v0 * v0;
                    ss[nf * 2 + 1] += v1 * v1;
                }
                u16 h0, l0, h1, l1;
                split_hl16(v0, h0, l0);
                split_hl16(v1, h1, l1);
                acc[mf][nf][half * 2] = __uint_as_float((u32)h0 | ((u32)h1 << 16));
                acc[mf][nf][half * 2 + 1] = __uint_as_float((u32)l0 | ((u32)l1 << 16));
            }
        }
    }
    #pragma unroll
    for (int nf = 0; nf < 8; nf++) {
        atomicAdd(&ssqs[colb + nf * 8], ss[nf * 2]);
        atomicAdd(&ssqs[colb + nf * 8 + 1], ss[nf * 2 + 1]);
    }

    // ---- staged coalesced store of hi then lo plane (128 rows x 64 u32, pad 68) ----
    u32* sp = (u32*)sm;
    int col32 = nw * 32 + (lane & 3);
    #pragma unroll
    for (int plane = 0; plane < 2; plane++) {
        __syncthreads();
        #pragma unroll
        for (int mf = 0; mf < 2; mf++)
            #pragma unroll
            for (int half = 0; half < 2; half++) {
                int row = mw * 32 + mf * 16 + half * 8 + (lane >> 2);
                #pragma unroll
                for (int nf = 0; nf < 8; nf++)
                    sp[row * 68 + col32 + nf * 4] =
                        __float_as_uint(acc[mf][nf][half * 2 + plane]);
            }
        __syncthreads();
        u32* gdst = (u32*)(plane == 0 ? g_hh : g_hl);
        #pragma unroll
        for (int q = 0; q < 8; q++) {
            int idx = q * 1024 + tid * 4;
            int row = idx >> 6, col = idx & 63;
            int gr = m0 + row;
            if (gr < N_SITES) {
                uint4 v = *(uint4*)&sp[row * 68 + col];
                *(uint4*)(gdst + (size_t)gr * 256 + nblk * 64 + col) = v;
            }
        }
    }
    __syncthreads();
    if (tid < 128) atomicAdd(&g_ssq[nblk * 128 + tid], ssqs[tid]);
}

// ---------------- GRN scale ----------------
__global__ void k_grn(const float* __restrict__ grn_g) {
    __shared__ float sh[HID];
    int t = threadIdx.x;  // 512
    float gx = sqrtf(g_ssq[t]);
    sh[t] = gx;
    __syncthreads();
    for (int o = 256; o; o >>= 1) {
        if (t < o) sh[t] += sh[t + o];
        __syncthreads();
    }
    float nx = gx / (sh[0] * (1.0f / HID) + 1e-6f);
    g_scale[t] = 1.0f + grn_g[t] * nx;
}

// ---------------- GEMM2: (h*scale) @ w2 -> + c2 + residual (staged) ----------------
__global__ __launch_bounds__(256) void k_gemm2(const float* __restrict__ feats,
                                               float* __restrict__ out) {
    extern __shared__ u16 sm[];
    int tid = threadIdx.x, lane = tid & 31, wid = tid >> 5;
    int mw = wid & 3, nw = wid >> 2;
    int m0 = blockIdx.x * 128;

    float acc[2][8][4];
    #pragma unroll
    for (int i = 0; i < 2; i++)
        #pragma unroll
        for (int j = 0; j < 8; j++)
            #pragma unroll
            for (int r = 0; r < 4; r++) acc[i][j][r] = 0.f;

    load_tile(sm, tid, 0, m0, g_hh, g_hl, HID, g_w2, DIM, 0);
    int stage = 0;
    #pragma unroll 1
    for (int kt = 0; kt < 16; kt++) {
        if (kt + 1 < 16) {
            load_tile(sm + (stage ^ 1) * SM_STAGE, tid, kt + 1, m0,
                      g_hh, g_hl, HID, g_w2, DIM, 0);
            asm volatile("cp.async.wait_group 1;\n");
        } else {
            asm volatile("cp.async.wait_group 0;\n");
        }
        __syncthreads();
        mma_tile(sm + stage * SM_STAGE, lane, mw, nw, acc);
        __syncthreads();
        stage ^= 1;
    }

    // ---- epilogue: + c2, stage in smem (128 x 128 fp32, pad 132), coalesced out ----
    int colb = nw * 64 + (lane & 3) * 2;
    float c2v[8][2];
    #pragma unroll
    for (int nf = 0; nf < 8; nf++) {
        c2v[nf][0] = g_c2[colb + nf * 8];
        c2v[nf][1] = g_c2[colb + nf * 8 + 1];
    }
    float* spf = (float*)sm;
    #pragma unroll
    for (int mf = 0; mf < 2; mf++)
        #pragma unroll
        for (int half = 0; half < 2; half++) {
            int row = mw * 32 + mf * 16 + half * 8 + (lane >> 2);
            #pragma unroll
            for (int nf = 0; nf < 8; nf++) {
                int col = colb + nf * 8;
                spf[row * 132 + col] = acc[mf][nf][half * 2] + c2v[nf][0];
                spf[row * 132 + col + 1] = acc[mf][nf][half * 2 + 1] + c2v[nf][1];
            }
        }
    __syncthreads();
    #pragma unroll
    for (int q = 0; q < 16; q++) {
        int idx = q * 1024 + tid * 4;
        int row = idx >> 7, col = idx & 127;
        int gr = m0 + row;
        if (gr < N_SITES) {
            float4 fv = *(const float4*)(feats + (size_t)gr * DIM + col);
            float4 sv = *(float4*)&spf[row * 132 + col];
            sv.x += fv.x; sv.y += fv.y; sv.z += fv.z; sv.w += fv.w;
            *(float4*)(out + (size_t)gr * DIM + col) = sv;
        }
    }
}

// ---------------- launch ----------------
extern "C" void kernel_launch(void* const* d_in, const int* in_sizes, int n_in,
                              void* d_out, int out_size) {
    const float* feats = (const float*)d_in[0];
    const int*   nidx  = (const int*)d_in[1];
    const float* dww   = (const float*)d_in[2];
    const float* dwb   = (const float*)d_in[3];
    const float* lng   = (const float*)d_in[4];
    const float* lnb   = (const float*)d_in[5];
    const float* w1    = (const float*)d_in[6];
    const float* b1    = (const float*)d_in[7];
    const float* grng  = (const float*)d_in[8];
    const float* grnb  = (const float*)d_in[9];
    const float* w2    = (const float*)d_in[10];
    const float* b2    = (const float*)d_in[11];
    float* out = (float*)d_out;

    cudaFuncSetAttribute(k_gemm1, cudaFuncAttributeMaxDynamicSharedMemorySize, SMEM1_BYTES);
    cudaFuncSetAttribute(k_gemm2, cudaFuncAttributeMaxDynamicSharedMemorySize, SMEM2_BYTES);

    k_init<<<1, 512>>>(grnb, w2, b2);
    k_w1prep<<<128, 512>>>(w1);
    k_dwln<<<(N_SITES * 32 + 255) / 256, 256>>>(feats, nidx, dww, dwb, lng, lnb);
    dim3 g1(4, (N_SITES + 127) / 128);
    k_gemm1<<<g1, 256, SMEM1_BYTES>>>(b1);
    k_grn<<<1, 512>>>(grng);
    k_w2prep<<<128, 512>>>(w2);
    k_gemm2<<<(N_SITES + 127) / 128, 256, SMEM2_BYTES>>>(feats, out);
}